// round 17
// baseline (speedup 1.0000x reference)
#include <cuda_runtime.h>
#include <stdint.h>

// ============================================================================
// Colorization L2Loss, two kernels.
//   loss = mean_b sum_{c,h,w} (in-tgt)^2 * prior[argmin_q d2(tgt_px, gamut[q])]
//
// Cell mapping (round-to-nearest, FP-magic): m = round(t*31.4) + 32 in [1,63],
//   as bits(fmaf(t, 31.4, 12582944.0)) & 63. Cell center t_c = (m-32)/31.4,
//   half-width r = 0.51/31.4 (inflated for binning FP slop).
// Build candidate filter (analytic 4-corner halfplane test): b is a candidate
//   iff d2(c,b) <= d2(c,b̂) + 2r(|Δx|+|Δy|) + eps (valid NN-superset for any
//   reference b̂; b̂ ~ argmin via packed 32-bit key reduce, exact d2 recomputed).
//   Emits u64/cell: 4 x u16 dup-padded ascending; slot3 sentinel 0xFFFF =>
//   overflow (~2% of cells), full list in g_cand/g_cnt.
// Loss (512 blk x 512 thr, 1 px/thread): NO pack-table smem copy — the 32KB
//   g_pack table is read directly through L1 (it is L1-resident on every SM;
//   LDG L1-hit ~ LDS latency). Smem holds only gamut points + 0.25-scaled
//   weights (5KB) -> occupancy limited by threads only (~100%). Per px:
//   FFMA/LOP cell -> LDG.64 pack (L1) -> 4x LDS.64 gathers -> direct d2
//   evals -> LDS.32 weight. Exact strict-< argmin (= argmin tie-break).
// ============================================================================

#define LGRID 64
#define NCELL (LGRID * LGRID)
#define CAP   32
#define MAXQ  320          // >= Q=313, exactly 10 warp-iterations
#define NIT   (MAXQ / 32)
#define CINV  (1.0f / 31.4f)
#define CMAGIC 12582944.0f // 2^23 + 2^22 + 32
#define CRAD  (0.51f / 31.4f)
#define TWOR  (2.0f * CRAD)

__device__ unsigned long long g_pack[NCELL];    // 32 KB, L1-resident in loss
__device__ unsigned short     g_cand[NCELL * CAP];
__device__ unsigned int       g_cnt[NCELL];

// ---------------------------------------------------------------------------
__global__ void __launch_bounds__(256) build_lut_kernel(
    const float2* __restrict__ gamut, float* __restrict__ out, int Q)
{
    __shared__ float2 sg[MAXQ];
    __shared__ unsigned short scand[8][CAP];

    if (blockIdx.x == 0 && threadIdx.x == 0) out[0] = 0.0f;

    for (int i = threadIdx.x; i < Q; i += 256) sg[i] = gamut[i];
    __syncthreads();

    const int warp = threadIdx.x >> 5;
    const int lane = threadIdx.x & 31;
    const int cell = blockIdx.x * 8 + warp;       // 512*8 = 4096 exactly

    const int ix = cell & (LGRID - 1);
    const int iy = cell >> 6;
    const float cx = (float)(ix - 32) * CINV;     // round-to-nearest bin center
    const float cy = (float)(iy - 32) * CINV;

    // --- pass 1: coords into registers, center d2, packed-key argmin --------
    float gx[NIT], gy[NIT], d2v[NIT];
    unsigned bkey = 0xFFFFFFFFu;
    #pragma unroll
    for (int j = 0; j < NIT; j++) {
        const int b = (j << 5) + lane;
        const float2 g = sg[b < Q ? b : 0];
        gx[j] = g.x;
        gy[j] = g.y;
        float d2 = 1e30f;
        if (b < Q) {
            const float dx = g.x - cx;
            const float dy = g.y - cy;
            d2 = fmaf(dx, dx, dy * dy);
        }
        d2v[j] = d2;
        // positive floats order as uints; low 9 bits carry the index.
        // approx argmin is fine: the filter is valid for ANY reference bin.
        bkey = min(bkey, (__float_as_uint(d2) & 0xFFFFFE00u) | (unsigned)b);
    }
    #pragma unroll
    for (int off = 16; off; off >>= 1)
        bkey = min(bkey, __shfl_xor_sync(0xFFFFFFFFu, bkey, off));

    const int bhat = (int)(bkey & 0x1FFu);
    const float2 gb = sg[bhat];
    float thr;
    {
        const float dx = gb.x - cx;
        const float dy = gb.y - cy;
        thr = fmaf(dx, dx, dy * dy) + 1e-5f;      // exact d2(c,b̂) + eps
    }

    // --- pass 2: register-only analytic corner filter + ballot compaction --
    int base = 0;
    #pragma unroll
    for (int j = 0; j < NIT; j++) {
        const float s = fabsf(gx[j] - gb.x) + fabsf(gy[j] - gb.y);
        const bool take = (d2v[j] <= fmaf(TWOR, s, thr));   // d2v=1e30 if b>=Q
        const unsigned m = __ballot_sync(0xFFFFFFFFu, take);
        if (take) {
            const int pos = base + __popc(m & ((1u << lane) - 1u));
            if (pos < CAP)
                scand[warp][pos] = (unsigned short)((j << 5) + lane);
        }
        base += __popc(m);
    }
    __syncwarp();

    if (base > 4) {                               // rare (~2% of cells)
        const int nw = min(base, CAP);
        for (int j = lane; j < nw; j += 32)
            g_cand[cell * CAP + j] = scand[warp][j];
        if (lane == 0) g_cnt[cell] = (unsigned)base;
    }
    if (lane == 0) {
        const unsigned long long i0 = scand[warp][0];      // base >= 1 (b̂)
        const unsigned long long i1 = (base > 1) ? scand[warp][1] : i0;
        const unsigned long long i2 = (base > 2) ? scand[warp][2] : i0;
        unsigned long long i3       = (base > 3) ? scand[warp][3] : i0;
        if (base > 4) i3 = 0xFFFFull;                      // overflow sentinel
        g_pack[cell] = i0 | (i1 << 16) | (i2 << 32) | (i3 << 48);
    }
}

// ---------------------------------------------------------------------------
// Loss: 512 blocks x 512 threads, ONE pixel per thread (262144 px).
// Pack table read directly from global (L1-resident); only 5KB smem.
// ---------------------------------------------------------------------------
__global__ void __launch_bounds__(512) loss_kernel(
    const float*  __restrict__ input,
    const float*  __restrict__ target,
    const float2* __restrict__ gamut,
    const float*  __restrict__ prior,
    float*        __restrict__ out,
    int Q)
{
    __shared__ float2 ssg[MAXQ];                  // 2.5 KB raw gamut points
    __shared__ float  ssw[MAXQ];                  // 1.25 KB weights (x0.25)
    __shared__ float  ws[16];

    // Pixel scalars issued first: latency hides under the sf table fill.
    const int q     = blockIdx.x * 512 + threadIdx.x;   // 0..262143
    const int bb    = q >> 16;
    const int n     = q & 65535;
    const int base0 = bb * 131072 + n;

    const float t0 = target[base0];
    const float t1 = target[base0 + 65536];
    const float i0 = input[base0];
    const float i1 = input[base0 + 65536];

    for (int i = threadIdx.x; i < Q; i += 512) {
        ssg[i] = gamut[i];
        ssw[i] = prior[i] * 0.25f;    // fold batch mean into the weight
    }
    __syncthreads();

    // Magic-number cell binning: m = round(31.4*t) + 32 in [1,63] = bits & 63.
    const int ixp = (int)(__float_as_uint(fmaf(t0, 31.4f, CMAGIC)) & 63u);
    const int iyp = (int)(__float_as_uint(fmaf(t1, 31.4f, CMAGIC)) & 63u);
    const int cc  = (iyp << 6) | ixp;

    const unsigned long long p = __ldg(&g_pack[cc]);    // L1-resident 32KB
    const unsigned a0 = (unsigned)(p & 0xFFFFull);
    const unsigned a1 = (unsigned)((p >> 16) & 0xFFFFull);
    const unsigned a2 = (unsigned)((p >> 32) & 0xFFFFull);
    const unsigned a3 = (unsigned)(p >> 48);

    float w;
    if (a3 != 0xFFFFu) {
        float2 g = ssg[a0];
        float dx = t0 - g.x, dy = t1 - g.y;
        float best = fmaf(dx, dx, dy * dy);
        unsigned bi = a0;

        g = ssg[a1]; dx = t0 - g.x; dy = t1 - g.y;
        float d = fmaf(dx, dx, dy * dy);
        if (d < best) { best = d; bi = a1; }

        g = ssg[a2]; dx = t0 - g.x; dy = t1 - g.y;
        d = fmaf(dx, dx, dy * dy);
        if (d < best) { best = d; bi = a2; }

        g = ssg[a3]; dx = t0 - g.x; dy = t1 - g.y;
        d = fmaf(dx, dx, dy * dy);
        if (d < best) { best = d; bi = a3; }

        w = ssw[bi];
    } else {
        // rare overflow cell (~2%): exact scan of the global list
        float best = 1e30f;
        unsigned bi = 0;
        const unsigned cnt = g_cnt[cc];
        if (cnt <= CAP) {
            const unsigned short* cl = &g_cand[cc * CAP];
            for (unsigned j = 0; j < cnt; j++) {
                const unsigned b = (unsigned)cl[j];
                const float2 g = ssg[b];
                const float dx = t0 - g.x, dy = t1 - g.y;
                const float d = fmaf(dx, dx, dy * dy);
                if (d < best) { best = d; bi = b; }
            }
        } else {
            for (int b = 0; b < Q; b++) {
                const float2 g = ssg[b];
                const float dx = t0 - g.x, dy = t1 - g.y;
                const float d = fmaf(dx, dx, dy * dy);
                if (d < best) { best = d; bi = (unsigned)b; }
            }
        }
        w = ssw[bi];
    }

    const float d0 = i0 - t0;
    const float d1 = i1 - t1;
    float acc = w * fmaf(d0, d0, d1 * d1);

    #pragma unroll
    for (int off = 16; off; off >>= 1)
        acc += __shfl_xor_sync(0xFFFFFFFFu, acc, off);

    if ((threadIdx.x & 31) == 0) ws[threadIdx.x >> 5] = acc;
    __syncthreads();
    if (threadIdx.x < 16) {
        float v = ws[threadIdx.x];
        #pragma unroll
        for (int off = 8; off; off >>= 1)
            v += __shfl_xor_sync(0xFFFFu, v, off);
        if (threadIdx.x == 0) atomicAdd(out, v);
    }
}

// ---------------------------------------------------------------------------
extern "C" void kernel_launch(void* const* d_in, const int* in_sizes, int n_in,
                              void* d_out, int out_size)
{
    const float*  input  = (const float*)d_in[0];
    const float*  target = (const float*)d_in[1];
    const float2* gamut  = (const float2*)d_in[2];   // [Q,2]
    const float*  prior  = (const float*)d_in[3];    // [Q]
    float* out = (float*)d_out;
    const int Q = in_sizes[3];                        // 313

    build_lut_kernel<<<NCELL / 8, 256>>>(gamut, out, Q);
    loss_kernel<<<512, 512>>>(input, target, gamut, prior, out, Q);
}